// round 12
// baseline (speedup 1.0000x reference)
#include <cuda_runtime.h>
#include <cuda_fp16.h>
#include <cstdint>

#define T_LEN 16384
#define DIM   1024
#define NCHUNK 256
#define CLEN   64

// ---------------- scratch (static device globals; no allocation) ----------------
__device__ __align__(16) float  g_gain[DIM];
__device__ float2 g_lam[DIM];
__device__ float2 g_lamL[DIM];
__device__ float2 g_carry [NCHUNK * DIM];
__device__ float2 g_carry2[NCHUNK * DIM];

// fp16 operands (all K-major: [row][k], k contiguous)
__device__ __align__(16) __half g_x16   [(size_t)T_LEN * DIM];   // X (fp16)
__device__ __align__(16) __half g_bure16[(size_t)T_LEN * DIM];   // Bu re
__device__ __align__(16) __half g_buim16[(size_t)T_LEN * DIM];   // Bu im
__device__ __align__(16) __half g_hre16 [(size_t)T_LEN * DIM];   // hidden re
__device__ __align__(16) __half g_him16 [(size_t)T_LEN * DIM];   // hidden im
__device__ __align__(16) __half g_brt16 [DIM * DIM];   // (B_re*gain)^T [h][i]
__device__ __align__(16) __half g_bit16 [DIM * DIM];   // (B_im*gain)^T [h][i]
__device__ __align__(16) __half g_cre16 [DIM * DIM];   // C_re          [o][h]
__device__ __align__(16) __half g_cin16 [DIM * DIM];   // -C_im         [o][h]
__device__ __align__(16) __half g_dt16  [DIM * DIM];   // D^T           [o][i]

// ---------------- PTX helpers ----------------
__device__ __forceinline__ unsigned smem_u32(const void* p) {
    unsigned a;
    asm("{ .reg .u64 t; cvta.to.shared.u64 t, %1; cvt.u32.u64 %0, t; }" : "=r"(a) : "l"(p));
    return a;
}
__device__ __forceinline__ void ldsm4(uint32_t* r, unsigned a) {
    asm volatile("ldmatrix.sync.aligned.m8n8.x4.shared.b16 {%0,%1,%2,%3}, [%4];"
        : "=r"(r[0]), "=r"(r[1]), "=r"(r[2]), "=r"(r[3]) : "r"(a));
}
__device__ __forceinline__ void mma16816(float* c, const uint32_t* a, uint32_t b0, uint32_t b1) {
    asm volatile(
        "mma.sync.aligned.m16n8k16.row.col.f32.f16.f16.f32 "
        "{%0,%1,%2,%3}, {%4,%5,%6,%7}, {%8,%9}, {%0,%1,%2,%3};"
        : "+f"(c[0]), "+f"(c[1]), "+f"(c[2]), "+f"(c[3])
        : "r"(a[0]), "r"(a[1]), "r"(a[2]), "r"(a[3]), "r"(b0), "r"(b1));
}
__device__ __forceinline__ void cp16(unsigned dst, const void* src) {
    asm volatile("cp.async.cg.shared.global [%0], [%1], 16;" :: "r"(dst), "l"(src) : "memory");
}
#define CP_COMMIT() asm volatile("cp.async.commit_group;" ::: "memory")
#define CP_WAIT1()  asm volatile("cp.async.wait_group 1;" ::: "memory")

// ---------------- setup ----------------
__global__ void setup_kernel(const float* __restrict__ nu_log,
                             const float* __restrict__ theta_log,
                             const float* __restrict__ gamma_log) {
    int h = blockIdx.x * blockDim.x + threadIdx.x;
    if (h >= DIM) return;
    float nu = expf(nu_log[h]);
    float th = expf(theta_log[h]);
    float r  = expf(-nu);
    float lr = r * cosf(th);
    float li = r * sinf(th);
    g_lam[h] = make_float2(lr, li);
    float ar = lr, ai = li;
#pragma unroll
    for (int s = 0; s < 6; s++) {
        float nr = ar * ar - ai * ai;
        float ni = 2.0f * ar * ai;
        ar = nr; ai = ni;
    }
    g_lamL[h] = make_float2(ar, ai);
    g_gain[h] = expf(gamma_log[h]);
}

// ---------------- prep: elementwise fp16 convert ----------------
// mode 0: X, 1: Cre, 2: -Cim
__global__ __launch_bounds__(256) void conv_mat(const float* __restrict__ src, int mode, int n) {
    int i = (blockIdx.x * blockDim.x + threadIdx.x) * 4;
    if (i >= n) return;
    float4 v = *(const float4*)(src + i);
    float sign = (mode == 2) ? -1.0f : 1.0f;
    __half h4[4];
    h4[0] = __float2half_rn(v.x * sign);
    h4[1] = __float2half_rn(v.y * sign);
    h4[2] = __float2half_rn(v.z * sign);
    h4[3] = __float2half_rn(v.w * sign);
    __half* dst = (mode == 0) ? g_x16 : (mode == 1 ? g_cre16 : g_cin16);
    *(uint2*)(dst + i) = *(uint2*)h4;
}

// ---------------- prep: transpose + fp16 (gain-scaled B_re/B_im; D) ----------------
__global__ void transpose_conv(const float* __restrict__ src, int mode) {
    __shared__ float tl[32][33];
    int bx = blockIdx.x * 32, by = blockIdx.y * 32;
    int tx = threadIdx.x, ty = threadIdx.y;
    bool use_gain = (mode != 2);
#pragma unroll
    for (int r = 0; r < 4; r++) {
        int row = by + ty + r * 8;
        float v = src[(size_t)row * DIM + bx + tx];
        if (use_gain) v *= g_gain[row];
        tl[ty + r * 8][tx] = v;
    }
    __syncthreads();
    __half* dst = (mode == 0) ? g_brt16 : (mode == 1 ? g_bit16 : g_dt16);
#pragma unroll
    for (int r = 0; r < 4; r++) {
        float v = tl[tx][ty + r * 8];
        size_t o = (size_t)(bx + ty + r * 8) * DIM + by + tx;
        dst[o] = __float2half_rn(v);
    }
}

// ================= generic TN fp16 GEMM, BM=BN=128, BK=64, 3-stage ring =================
// smem: 3 x (A 16KB + B 16KB) = 96KB; regs capped for 2 CTAs/SM.
// mode 0: Bu (z = re/im, fp16 store). mode 1: C-term, accumulate into out.
// mode 2: D-term, write out.

__device__ __forceinline__ void pass_ptrs(int mode, int z, int kt,
        const __half*& A, const __half*& B, int& k0) {
    if (mode == 0) {
        A = g_x16; B = z ? g_bit16 : g_brt16; k0 = kt * 64;
    } else if (mode == 1) {
        int p = kt >> 4; k0 = (kt & 15) * 64;
        A = p ? g_him16 : g_hre16;
        B = p ? g_cin16 : g_cre16;
    } else {
        A = g_x16; B = g_dt16; k0 = kt * 64;
    }
}

__global__ __launch_bounds__(256, 2) void gemm_mma(int mode, float* __restrict__ outp) {
    extern __shared__ __align__(128) char sm[];
    unsigned sbase = smem_u32(sm);
    const int tid = threadIdx.x, lane = tid & 31, w = tid >> 5;
    const int wm = w & 1, wn = w >> 1;
    const int n0 = blockIdx.x * 128, m0 = blockIdx.y * 128;
    const int z  = blockIdx.z;
    const int NK = (mode == 1) ? 32 : 16;

    float c[4][4][4];
#pragma unroll
    for (int a = 0; a < 4; a++)
#pragma unroll
        for (int b = 0; b < 4; b++)
#pragma unroll
            for (int d = 0; d < 4; d++) c[a][b][d] = 0.f;

    auto load_stage = [&](int stage, int kt) {
        const __half *A, *B; int k0;
        pass_ptrs(mode, z, kt, A, B, k0);
        unsigned sb = sbase + stage * 32768;
#pragma unroll
        for (int i = 0; i < 4; i++) {
            int idx = tid + i * 256; int row = idx >> 3, g = idx & 7;
            unsigned sw = (unsigned)(row * 128 + ((g ^ (row & 7)) << 4));
            cp16(sb + sw, A + (size_t)(m0 + row) * DIM + k0 + g * 8);
            cp16(sb + 16384 + sw, B + (size_t)(n0 + row) * DIM + k0 + g * 8);
        }
    };

    load_stage(0, 0); CP_COMMIT();
    load_stage(1, 1); CP_COMMIT();

    const int lr = lane & 15, lh = lane >> 4;
    int st = 0;                         // stage holding tile kt
    for (int kt = 0; kt < NK; kt++) {
        CP_WAIT1();
        __syncthreads();
        // issue next load into the free stage BEFORE compute
        if (kt + 2 < NK) {
            int free_st = st + 2; if (free_st >= 3) free_st -= 3;
            load_stage(free_st, kt + 2);
        }
        CP_COMMIT();
        unsigned sA = sbase + st * 32768;
        unsigned sB = sA + 16384;
#pragma unroll
        for (int ks = 0; ks < 4; ks++) {
            int kg = ks * 2 + lh;
            uint32_t bb[2][4];
#pragma unroll
            for (int nh = 0; nh < 2; nh++) {
                int row = wn * 32 + nh * 16 + lr;
                ldsm4(bb[nh], sB + row * 128 + ((kg ^ (row & 7)) << 4));
            }
            // one A fragment live at a time (register pressure: 2 CTAs/SM)
#pragma unroll
            for (int mf = 0; mf < 4; mf++) {
                uint32_t a[4];
                int row = wm * 64 + mf * 16 + lr;
                ldsm4(a, sA + row * 128 + ((kg ^ (row & 7)) << 4));
                mma16816(c[mf][0], a, bb[0][0], bb[0][2]);
                mma16816(c[mf][1], a, bb[0][1], bb[0][3]);
                mma16816(c[mf][2], a, bb[1][0], bb[1][2]);
                mma16816(c[mf][3], a, bb[1][1], bb[1][3]);
            }
        }
        st++; if (st >= 3) st = 0;
    }

    if (mode == 0) {
        __half* dst = z ? g_buim16 : g_bure16;
#pragma unroll
        for (int mf = 0; mf < 4; mf++) {
#pragma unroll
            for (int nf = 0; nf < 4; nf++) {
                int r   = wm * 64 + mf * 16 + (lane >> 2);
                int col = wn * 32 + nf * 8  + (lane & 3) * 2;
                size_t o = (size_t)(m0 + r) * DIM + n0 + col;
                *(__half2*)(dst + o) = __floats2half2_rn(c[mf][nf][0], c[mf][nf][1]);
                *(__half2*)(dst + o + 8 * DIM) = __floats2half2_rn(c[mf][nf][2], c[mf][nf][3]);
            }
        }
    } else if (mode == 2) {
#pragma unroll
        for (int mf = 0; mf < 4; mf++) {
#pragma unroll
            for (int nf = 0; nf < 4; nf++) {
                int r   = wm * 64 + mf * 16 + (lane >> 2);
                int col = wn * 32 + nf * 8  + (lane & 3) * 2;
                size_t o = (size_t)(m0 + r) * DIM + n0 + col;
                *(float2*)(outp + o) = make_float2(c[mf][nf][0], c[mf][nf][1]);
                *(float2*)(outp + o + 8 * DIM) = make_float2(c[mf][nf][2], c[mf][nf][3]);
            }
        }
    } else {   // mode 1: accumulate C-term onto D-term already in out
#pragma unroll
        for (int mf = 0; mf < 4; mf++) {
#pragma unroll
            for (int nf = 0; nf < 4; nf++) {
                int r   = wm * 64 + mf * 16 + (lane >> 2);
                int col = wn * 32 + nf * 8  + (lane & 3) * 2;
                size_t o = (size_t)(m0 + r) * DIM + n0 + col;
                float2 p0 = *(float2*)(outp + o);
                float2 p1 = *(float2*)(outp + o + 8 * DIM);
                *(float2*)(outp + o) = make_float2(p0.x + c[mf][nf][0], p0.y + c[mf][nf][1]);
                *(float2*)(outp + o + 8 * DIM) = make_float2(p1.x + c[mf][nf][2], p1.y + c[mf][nf][3]);
            }
        }
    }
}

// ---------------- scan pass 1: chunk carries only (read-only on Bu) ----------------
__global__ __launch_bounds__(256) void scan_carry() {
    int h = blockIdx.y * blockDim.x + threadIdx.x;
    int c = blockIdx.x;
    float2 lam = g_lam[h];
    float ar = 0.f, ai = 0.f;
    size_t idx = (size_t)c * CLEN * DIM + h;
#pragma unroll 4
    for (int t = 0; t < CLEN; t++, idx += DIM) {
        float br = __half2float(g_bure16[idx]);
        float bi = __half2float(g_buim16[idx]);
        float nr = fmaf(lam.x, ar, fmaf(-lam.y, ai, br));
        float ni = fmaf(lam.x, ai, fmaf( lam.y, ar, bi));
        ar = nr; ai = ni;
    }
    g_carry[c * DIM + h] = make_float2(ar, ai);
}

// ---------------- scan pass 2: prefix over chunk carries (batched loads for MLP) ----------------
__global__ __launch_bounds__(256) void scan_chunks() {
    int h = blockIdx.x * blockDim.x + threadIdx.x;
    float2 lamL = g_lamL[h];
    float pr = 0.f, pi = 0.f;
    for (int cb = 0; cb < NCHUNK; cb += 32) {
        float2 e[32];
#pragma unroll
        for (int j = 0; j < 32; j++) e[j] = g_carry[(cb + j) * DIM + h];
#pragma unroll
        for (int j = 0; j < 32; j++) {
            float nr = fmaf(lamL.x, pr, fmaf(-lamL.y, pi, e[j].x));
            float ni = fmaf(lamL.x, pi, fmaf( lamL.y, pr, e[j].y));
            pr = nr; pi = ni;
            e[j] = make_float2(pr, pi);
        }
#pragma unroll
        for (int j = 0; j < 32; j++) g_carry2[(cb + j) * DIM + h] = e[j];
    }
}

// ---------------- scan pass 3: rerun recurrence with carry-in, write fp16 H ----------------
__global__ __launch_bounds__(256) void scan_apply_all() {
    int h = blockIdx.y * blockDim.x + threadIdx.x;
    int c = blockIdx.x;
    float2 P = (c == 0) ? make_float2(0.f, 0.f) : g_carry2[(c - 1) * DIM + h];
    float2 lam = g_lam[h];
    float ar = P.x, ai = P.y;
    size_t idx = (size_t)c * CLEN * DIM + h;
#pragma unroll 4
    for (int t = 0; t < CLEN; t++, idx += DIM) {
        float br = __half2float(g_bure16[idx]);
        float bi = __half2float(g_buim16[idx]);
        float nr = fmaf(lam.x, ar, fmaf(-lam.y, ai, br));
        float ni = fmaf(lam.x, ai, fmaf( lam.y, ar, bi));
        ar = nr; ai = ni;
        g_hre16[idx] = __float2half_rn(ar);
        g_him16[idx] = __float2half_rn(ai);
    }
}

// ---------------- launch (fork AFTER GEMM1: D-GEMM overlaps the scan only) ----------------
extern "C" void kernel_launch(void* const* d_in, const int* in_sizes, int n_in,
                              void* d_out, int out_size) {
    const float* X         = (const float*)d_in[0];
    const float* nu_log    = (const float*)d_in[1];
    const float* theta_log = (const float*)d_in[2];
    const float* gamma_log = (const float*)d_in[3];
    const float* Bre       = (const float*)d_in[4];
    const float* Bim       = (const float*)d_in[5];
    const float* Cre       = (const float*)d_in[6];
    const float* Cim       = (const float*)d_in[7];
    const float* Dm        = (const float*)d_in[8];
    float* out             = (float*)d_out;

    cudaFuncSetAttribute(gemm_mma, cudaFuncAttributeMaxDynamicSharedMemorySize, 98304);

    // Side stream + events, created fresh per call and intentionally leaked
    // (kernel_launch runs twice total; no tracked device-memory allocation).
    cudaStream_t s2;
    cudaStreamCreate(&s2);
    cudaEvent_t evFork, evJoin;
    cudaEventCreateWithFlags(&evFork, cudaEventDisableTiming);
    cudaEventCreateWithFlags(&evJoin, cudaEventDisableTiming);

    // ---- prep (main stream) ----
    setup_kernel<<<4, 256>>>(nu_log, theta_log, gamma_log);
    conv_mat<<<T_LEN * DIM / 4 / 256, 256>>>(X, 0, T_LEN * DIM);
    conv_mat<<<DIM * DIM / 4 / 256, 256>>>(Cre, 1, DIM * DIM);
    conv_mat<<<DIM * DIM / 4 / 256, 256>>>(Cim, 2, DIM * DIM);
    transpose_conv<<<dim3(32, 32), dim3(32, 8)>>>(Bre, 0);
    transpose_conv<<<dim3(32, 32), dim3(32, 8)>>>(Bim, 1);
    transpose_conv<<<dim3(32, 32), dim3(32, 8)>>>(Dm, 2);

    // ---- GEMM1 (serial; full machine) ----
    gemm_mma<<<dim3(DIM / 128, T_LEN / 128, 2), 256, 98304>>>(0, nullptr);

    // ---- fork AFTER GEMM1: D-GEMM fills the scan's tensor-idle window ----
    cudaEventRecord(evFork, 0);
    cudaStreamWaitEvent(s2, evFork, 0);
    gemm_mma<<<dim3(DIM / 128, T_LEN / 128, 1), 256, 98304, s2>>>(2, out);
    cudaEventRecord(evJoin, s2);

    // ---- scan chain (main stream, memory-bound) ----
    scan_carry<<<dim3(NCHUNK, DIM / 256), 256>>>();
    scan_chunks<<<DIM / 256, 256>>>();
    scan_apply_all<<<dim3(NCHUNK, DIM / 256), 256>>>();

    // ---- join, then C-GEMM accumulates onto D result in out ----
    cudaStreamWaitEvent(0, evJoin, 0);
    gemm_mma<<<dim3(DIM / 128, T_LEN / 128, 1), 256, 98304>>>(1, out);
}

// round 13
// speedup vs baseline: 1.0464x; 1.0464x over previous
#include <cuda_runtime.h>
#include <cuda_fp16.h>
#include <cstdint>

#define T_LEN 16384
#define DIM   1024
#define NCHUNK 256
#define CLEN   64

// ---------------- scratch (static device globals; no allocation) ----------------
__device__ __align__(16) float  g_gain[DIM];
__device__ float2 g_lam[DIM];
__device__ float2 g_lamL[DIM];
__device__ float2 g_carry [NCHUNK * DIM];
__device__ float2 g_carry2[NCHUNK * DIM];

// fp16 operands (all K-major: [row][k], k contiguous)
__device__ __align__(16) __half g_x16   [(size_t)T_LEN * DIM];   // X (fp16)
__device__ __align__(16) __half g_bure16[(size_t)T_LEN * DIM];   // Bu re
__device__ __align__(16) __half g_buim16[(size_t)T_LEN * DIM];   // Bu im
__device__ __align__(16) __half g_hre16 [(size_t)T_LEN * DIM];   // hidden re
__device__ __align__(16) __half g_him16 [(size_t)T_LEN * DIM];   // hidden im
__device__ __align__(16) __half g_brt16 [DIM * DIM];   // (B_re*gain)^T [h][i]
__device__ __align__(16) __half g_bit16 [DIM * DIM];   // (B_im*gain)^T [h][i]
__device__ __align__(16) __half g_cre16 [DIM * DIM];   // C_re          [o][h]
__device__ __align__(16) __half g_cin16 [DIM * DIM];   // -C_im         [o][h]
__device__ __align__(16) __half g_dt16  [DIM * DIM];   // D^T           [o][i]

// ---------------- PTX helpers ----------------
__device__ __forceinline__ unsigned smem_u32(const void* p) {
    unsigned a;
    asm("{ .reg .u64 t; cvta.to.shared.u64 t, %1; cvt.u32.u64 %0, t; }" : "=r"(a) : "l"(p));
    return a;
}
__device__ __forceinline__ void ldsm4(uint32_t* r, unsigned a) {
    asm volatile("ldmatrix.sync.aligned.m8n8.x4.shared.b16 {%0,%1,%2,%3}, [%4];"
        : "=r"(r[0]), "=r"(r[1]), "=r"(r[2]), "=r"(r[3]) : "r"(a));
}
__device__ __forceinline__ void mma16816(float* c, const uint32_t* a, uint32_t b0, uint32_t b1) {
    asm volatile(
        "mma.sync.aligned.m16n8k16.row.col.f32.f16.f16.f32 "
        "{%0,%1,%2,%3}, {%4,%5,%6,%7}, {%8,%9}, {%0,%1,%2,%3};"
        : "+f"(c[0]), "+f"(c[1]), "+f"(c[2]), "+f"(c[3])
        : "r"(a[0]), "r"(a[1]), "r"(a[2]), "r"(a[3]), "r"(b0), "r"(b1));
}
__device__ __forceinline__ void cp16(unsigned dst, const void* src) {
    asm volatile("cp.async.cg.shared.global [%0], [%1], 16;" :: "r"(dst), "l"(src) : "memory");
}
#define CP_COMMIT() asm volatile("cp.async.commit_group;" ::: "memory")
#define CP_WAIT1()  asm volatile("cp.async.wait_group 1;" ::: "memory")

// ---------------- setup ----------------
__global__ void setup_kernel(const float* __restrict__ nu_log,
                             const float* __restrict__ theta_log,
                             const float* __restrict__ gamma_log) {
    int h = blockIdx.x * blockDim.x + threadIdx.x;
    if (h >= DIM) return;
    float nu = expf(nu_log[h]);
    float th = expf(theta_log[h]);
    float r  = expf(-nu);
    float lr = r * cosf(th);
    float li = r * sinf(th);
    g_lam[h] = make_float2(lr, li);
    float ar = lr, ai = li;
#pragma unroll
    for (int s = 0; s < 6; s++) {
        float nr = ar * ar - ai * ai;
        float ni = 2.0f * ar * ai;
        ar = nr; ai = ni;
    }
    g_lamL[h] = make_float2(ar, ai);
    g_gain[h] = expf(gamma_log[h]);
}

// ---------------- prep: X -> fp16 ----------------
__global__ __launch_bounds__(256) void conv_x(const float* __restrict__ src, int n) {
    int i = (blockIdx.x * blockDim.x + threadIdx.x) * 4;
    if (i >= n) return;
    float4 v = *(const float4*)(src + i);
    __half h4[4];
    h4[0] = __float2half_rn(v.x);
    h4[1] = __float2half_rn(v.y);
    h4[2] = __float2half_rn(v.z);
    h4[3] = __float2half_rn(v.w);
    *(uint2*)(g_x16 + i) = *(uint2*)h4;
}

// ---------------- prep: Cre -> g_cre16, -Cim -> g_cin16 (fused, grid.y=2) ----------------
__global__ __launch_bounds__(256) void conv_c(const float* __restrict__ Cre,
                                              const float* __restrict__ Cim) {
    int z = blockIdx.y;
    const float* src = z ? Cim : Cre;
    __half* dst = z ? g_cin16 : g_cre16;
    float sign = z ? -1.0f : 1.0f;
    int i = (blockIdx.x * blockDim.x + threadIdx.x) * 4;
    float4 v = *(const float4*)(src + i);
    __half h4[4];
    h4[0] = __float2half_rn(v.x * sign);
    h4[1] = __float2half_rn(v.y * sign);
    h4[2] = __float2half_rn(v.z * sign);
    h4[3] = __float2half_rn(v.w * sign);
    *(uint2*)(dst + i) = *(uint2*)h4;
}

// ---------------- prep: transpose + fp16 for Bre/Bim (gain-scaled) and D (fused, grid.z=3) ----------------
__global__ void transpose_conv(const float* __restrict__ Bre,
                               const float* __restrict__ Bim,
                               const float* __restrict__ Dm) {
    __shared__ float tl[32][33];
    int mode = blockIdx.z;
    const float* src = (mode == 0) ? Bre : (mode == 1 ? Bim : Dm);
    __half* dst = (mode == 0) ? g_brt16 : (mode == 1 ? g_bit16 : g_dt16);
    bool use_gain = (mode != 2);
    int bx = blockIdx.x * 32, by = blockIdx.y * 32;
    int tx = threadIdx.x, ty = threadIdx.y;
#pragma unroll
    for (int r = 0; r < 4; r++) {
        int row = by + ty + r * 8;
        float v = src[(size_t)row * DIM + bx + tx];
        if (use_gain) v *= g_gain[row];
        tl[ty + r * 8][tx] = v;
    }
    __syncthreads();
#pragma unroll
    for (int r = 0; r < 4; r++) {
        float v = tl[tx][ty + r * 8];
        size_t o = (size_t)(bx + ty + r * 8) * DIM + by + tx;
        dst[o] = __float2half_rn(v);
    }
}

// ================= generic TN fp16 GEMM, BM=BN=128, BK=64, 3-stage ring =================
// smem: 3 x (A 16KB + B 16KB) = 96KB; regs capped for 2 CTAs/SM.
// mode 0: Bu (z = re/im, fp16 store). mode 1: out = C-term + D-term (3 fused passes).

__device__ __forceinline__ void pass_ptrs(int mode, int z, int kt,
        const __half*& A, const __half*& B, int& k0) {
    if (mode == 0) {
        A = g_x16; B = z ? g_bit16 : g_brt16; k0 = kt * 64;
    } else {
        int p = kt >> 4; k0 = (kt & 15) * 64;
        switch (p) {
            case 0:  A = g_hre16; B = g_cre16; break;
            case 1:  A = g_him16; B = g_cin16; break;
            default: A = g_x16;   B = g_dt16;  break;
        }
    }
}

__global__ __launch_bounds__(256, 2) void gemm_mma(int mode, float* __restrict__ outp) {
    extern __shared__ __align__(128) char sm[];
    unsigned sbase = smem_u32(sm);
    const int tid = threadIdx.x, lane = tid & 31, w = tid >> 5;
    const int wm = w & 1, wn = w >> 1;
    const int n0 = blockIdx.x * 128, m0 = blockIdx.y * 128;
    const int z  = blockIdx.z;
    const int NK = (mode == 0) ? 16 : 48;

    float c[4][4][4];
#pragma unroll
    for (int a = 0; a < 4; a++)
#pragma unroll
        for (int b = 0; b < 4; b++)
#pragma unroll
            for (int d = 0; d < 4; d++) c[a][b][d] = 0.f;

    auto load_stage = [&](int stage, int kt) {
        const __half *A, *B; int k0;
        pass_ptrs(mode, z, kt, A, B, k0);
        unsigned sb = sbase + stage * 32768;
#pragma unroll
        for (int i = 0; i < 4; i++) {
            int idx = tid + i * 256; int row = idx >> 3, g = idx & 7;
            unsigned sw = (unsigned)(row * 128 + ((g ^ (row & 7)) << 4));
            cp16(sb + sw, A + (size_t)(m0 + row) * DIM + k0 + g * 8);
            cp16(sb + 16384 + sw, B + (size_t)(n0 + row) * DIM + k0 + g * 8);
        }
    };

    load_stage(0, 0); CP_COMMIT();
    load_stage(1, 1); CP_COMMIT();

    const int lr = lane & 15, lh = lane >> 4;
    int st = 0;                         // stage holding tile kt
    for (int kt = 0; kt < NK; kt++) {
        CP_WAIT1();
        __syncthreads();
        // issue next load into the free stage BEFORE compute
        if (kt + 2 < NK) {
            int free_st = st + 2; if (free_st >= 3) free_st -= 3;
            load_stage(free_st, kt + 2);
        }
        CP_COMMIT();
        unsigned sA = sbase + st * 32768;
        unsigned sB = sA + 16384;
#pragma unroll
        for (int ks = 0; ks < 4; ks++) {
            int kg = ks * 2 + lh;
            uint32_t bb[2][4];
#pragma unroll
            for (int nh = 0; nh < 2; nh++) {
                int row = wn * 32 + nh * 16 + lr;
                ldsm4(bb[nh], sB + row * 128 + ((kg ^ (row & 7)) << 4));
            }
            // one A fragment live at a time (register pressure: 2 CTAs/SM)
#pragma unroll
            for (int mf = 0; mf < 4; mf++) {
                uint32_t a[4];
                int row = wm * 64 + mf * 16 + lr;
                ldsm4(a, sA + row * 128 + ((kg ^ (row & 7)) << 4));
                mma16816(c[mf][0], a, bb[0][0], bb[0][2]);
                mma16816(c[mf][1], a, bb[0][1], bb[0][3]);
                mma16816(c[mf][2], a, bb[1][0], bb[1][2]);
                mma16816(c[mf][3], a, bb[1][1], bb[1][3]);
            }
        }
        st++; if (st >= 3) st = 0;
    }

    if (mode == 0) {
        __half* dst = z ? g_buim16 : g_bure16;
#pragma unroll
        for (int mf = 0; mf < 4; mf++) {
#pragma unroll
            for (int nf = 0; nf < 4; nf++) {
                int r   = wm * 64 + mf * 16 + (lane >> 2);
                int col = wn * 32 + nf * 8  + (lane & 3) * 2;
                size_t o = (size_t)(m0 + r) * DIM + n0 + col;
                *(__half2*)(dst + o) = __floats2half2_rn(c[mf][nf][0], c[mf][nf][1]);
                *(__half2*)(dst + o + 8 * DIM) = __floats2half2_rn(c[mf][nf][2], c[mf][nf][3]);
            }
        }
    } else {
#pragma unroll
        for (int mf = 0; mf < 4; mf++) {
#pragma unroll
            for (int nf = 0; nf < 4; nf++) {
                int r   = wm * 64 + mf * 16 + (lane >> 2);
                int col = wn * 32 + nf * 8  + (lane & 3) * 2;
                size_t o = (size_t)(m0 + r) * DIM + n0 + col;
                *(float2*)(outp + o) = make_float2(c[mf][nf][0], c[mf][nf][1]);
                *(float2*)(outp + o + 8 * DIM) = make_float2(c[mf][nf][2], c[mf][nf][3]);
            }
        }
    }
}

// ---------------- scan pass 1: chunk carries (2 channels/thread via __half2, MLP 8) ----------------
__global__ __launch_bounds__(256) void scan_carry() {
    int hp = blockIdx.y * blockDim.x + threadIdx.x;   // channel-pair index
    int h  = hp * 2;
    int c  = blockIdx.x;
    float2 lam0 = g_lam[h], lam1 = g_lam[h + 1];
    float ar0 = 0.f, ai0 = 0.f, ar1 = 0.f, ai1 = 0.f;
    size_t idx = (size_t)c * CLEN * DIM + h;
#pragma unroll 8
    for (int t = 0; t < CLEN; t++, idx += DIM) {
        __half2 br2 = *(const __half2*)(g_bure16 + idx);
        __half2 bi2 = *(const __half2*)(g_buim16 + idx);
        float2 br = __half22float2(br2);
        float2 bi = __half22float2(bi2);
        float nr0 = fmaf(lam0.x, ar0, fmaf(-lam0.y, ai0, br.x));
        float ni0 = fmaf(lam0.x, ai0, fmaf( lam0.y, ar0, bi.x));
        ar0 = nr0; ai0 = ni0;
        float nr1 = fmaf(lam1.x, ar1, fmaf(-lam1.y, ai1, br.y));
        float ni1 = fmaf(lam1.x, ai1, fmaf( lam1.y, ar1, bi.y));
        ar1 = nr1; ai1 = ni1;
    }
    *(float4*)(&g_carry[c * DIM + h]) = make_float4(ar0, ai0, ar1, ai1);
}

// ---------------- scan pass 2: prefix over chunk carries (batched loads for MLP) ----------------
__global__ __launch_bounds__(256) void scan_chunks() {
    int h = blockIdx.x * blockDim.x + threadIdx.x;
    float2 lamL = g_lamL[h];
    float pr = 0.f, pi = 0.f;
    for (int cb = 0; cb < NCHUNK; cb += 32) {
        float2 e[32];
#pragma unroll
        for (int j = 0; j < 32; j++) e[j] = g_carry[(cb + j) * DIM + h];
#pragma unroll
        for (int j = 0; j < 32; j++) {
            float nr = fmaf(lamL.x, pr, fmaf(-lamL.y, pi, e[j].x));
            float ni = fmaf(lamL.x, pi, fmaf( lamL.y, pr, e[j].y));
            pr = nr; pi = ni;
            e[j] = make_float2(pr, pi);
        }
#pragma unroll
        for (int j = 0; j < 32; j++) g_carry2[(cb + j) * DIM + h] = e[j];
    }
}

// ---------------- scan pass 3: apply carry, write fp16 H (2 channels/thread) ----------------
__global__ __launch_bounds__(256) void scan_apply_all() {
    int hp = blockIdx.y * blockDim.x + threadIdx.x;
    int h  = hp * 2;
    int c  = blockIdx.x;
    float4 Pv = (c == 0) ? make_float4(0.f, 0.f, 0.f, 0.f)
                         : *(const float4*)(&g_carry2[(c - 1) * DIM + h]);
    float2 lam0 = g_lam[h], lam1 = g_lam[h + 1];
    float ar0 = Pv.x, ai0 = Pv.y, ar1 = Pv.z, ai1 = Pv.w;
    size_t idx = (size_t)c * CLEN * DIM + h;
#pragma unroll 8
    for (int t = 0; t < CLEN; t++, idx += DIM) {
        __half2 br2 = *(const __half2*)(g_bure16 + idx);
        __half2 bi2 = *(const __half2*)(g_buim16 + idx);
        float2 br = __half22float2(br2);
        float2 bi = __half22float2(bi2);
        float nr0 = fmaf(lam0.x, ar0, fmaf(-lam0.y, ai0, br.x));
        float ni0 = fmaf(lam0.x, ai0, fmaf( lam0.y, ar0, bi.x));
        ar0 = nr0; ai0 = ni0;
        float nr1 = fmaf(lam1.x, ar1, fmaf(-lam1.y, ai1, br.y));
        float ni1 = fmaf(lam1.x, ai1, fmaf( lam1.y, ar1, bi.y));
        ar1 = nr1; ai1 = ni1;
        *(__half2*)(g_hre16 + idx) = __floats2half2_rn(ar0, ar1);
        *(__half2*)(g_him16 + idx) = __floats2half2_rn(ai0, ai1);
    }
}

// ---------------- launch (serial chain; overlap abandoned after R11/R12) ----------------
extern "C" void kernel_launch(void* const* d_in, const int* in_sizes, int n_in,
                              void* d_out, int out_size) {
    const float* X         = (const float*)d_in[0];
    const float* nu_log    = (const float*)d_in[1];
    const float* theta_log = (const float*)d_in[2];
    const float* gamma_log = (const float*)d_in[3];
    const float* Bre       = (const float*)d_in[4];
    const float* Bim       = (const float*)d_in[5];
    const float* Cre       = (const float*)d_in[6];
    const float* Cim       = (const float*)d_in[7];
    const float* Dm        = (const float*)d_in[8];
    float* out             = (float*)d_out;

    cudaFuncSetAttribute(gemm_mma, cudaFuncAttributeMaxDynamicSharedMemorySize, 98304);

    setup_kernel<<<4, 256>>>(nu_log, theta_log, gamma_log);
    conv_x<<<T_LEN * DIM / 4 / 256, 256>>>(X, T_LEN * DIM);
    conv_c<<<dim3(DIM * DIM / 4 / 256, 2), 256>>>(Cre, Cim);
    transpose_conv<<<dim3(32, 32, 3), dim3(32, 8)>>>(Bre, Bim, Dm);

    // GEMM1: Bu_re / Bu_im via blockIdx.z, fp16 output
    gemm_mma<<<dim3(DIM / 128, T_LEN / 128, 2), 256, 98304>>>(0, nullptr);

    scan_carry<<<dim3(NCHUNK, DIM / 512), 256>>>();
    scan_chunks<<<DIM / 256, 256>>>();
    scan_apply_all<<<dim3(NCHUNK, DIM / 512), 256>>>();

    // GEMM2: out = Hr@Cre^T + Hi@(-Cim)^T + X@D  (3 fused passes, 48 k-tiles)
    gemm_mma<<<dim3(DIM / 128, T_LEN / 128, 1), 256, 98304>>>(1, out);
}

// round 14
// speedup vs baseline: 1.0476x; 1.0012x over previous
#include <cuda_runtime.h>
#include <cuda_fp16.h>
#include <cstdint>

#define T_LEN 16384
#define DIM   1024
#define NCHUNK 256
#define CLEN   64

// ---------------- scratch (static device globals; no allocation) ----------------
__device__ __align__(16) float  g_gain[DIM];
__device__ float2 g_lam[DIM];
__device__ float2 g_lamL[DIM];
__device__ float2 g_carry [NCHUNK * DIM];
__device__ float2 g_carry2[NCHUNK * DIM];

// fp16 operands (all K-major: [row][k], k contiguous)
__device__ __align__(16) __half g_x16   [(size_t)T_LEN * DIM];   // X (fp16)
__device__ __align__(16) __half g_bure16[(size_t)T_LEN * DIM];   // Bu re
__device__ __align__(16) __half g_buim16[(size_t)T_LEN * DIM];   // Bu im
__device__ __align__(16) __half g_hre16 [(size_t)T_LEN * DIM];   // hidden re
__device__ __align__(16) __half g_him16 [(size_t)T_LEN * DIM];   // hidden im
__device__ __align__(16) __half g_brt16 [DIM * DIM];   // (B_re*gain)^T [h][i]
__device__ __align__(16) __half g_bit16 [DIM * DIM];   // (B_im*gain)^T [h][i]
__device__ __align__(16) __half g_cre16 [DIM * DIM];   // C_re          [o][h]
__device__ __align__(16) __half g_cin16 [DIM * DIM];   // -C_im         [o][h]
__device__ __align__(16) __half g_dt16  [DIM * DIM];   // D^T           [o][i]

// ---------------- PTX helpers ----------------
__device__ __forceinline__ unsigned smem_u32(const void* p) {
    unsigned a;
    asm("{ .reg .u64 t; cvta.to.shared.u64 t, %1; cvt.u32.u64 %0, t; }" : "=r"(a) : "l"(p));
    return a;
}
__device__ __forceinline__ void ldsm4(uint32_t* r, unsigned a) {
    asm volatile("ldmatrix.sync.aligned.m8n8.x4.shared.b16 {%0,%1,%2,%3}, [%4];"
        : "=r"(r[0]), "=r"(r[1]), "=r"(r[2]), "=r"(r[3]) : "r"(a));
}
__device__ __forceinline__ void mma16816(float* c, const uint32_t* a, uint32_t b0, uint32_t b1) {
    asm volatile(
        "mma.sync.aligned.m16n8k16.row.col.f32.f16.f16.f32 "
        "{%0,%1,%2,%3}, {%4,%5,%6,%7}, {%8,%9}, {%0,%1,%2,%3};"
        : "+f"(c[0]), "+f"(c[1]), "+f"(c[2]), "+f"(c[3])
        : "r"(a[0]), "r"(a[1]), "r"(a[2]), "r"(a[3]), "r"(b0), "r"(b1));
}
__device__ __forceinline__ void cp16(unsigned dst, const void* src) {
    asm volatile("cp.async.cg.shared.global [%0], [%1], 16;" :: "r"(dst), "l"(src) : "memory");
}
#define CP_COMMIT() asm volatile("cp.async.commit_group;" ::: "memory")
#define CP_WAIT1()  asm volatile("cp.async.wait_group 1;" ::: "memory")

// ---------------- setup ----------------
__global__ void setup_kernel(const float* __restrict__ nu_log,
                             const float* __restrict__ theta_log,
                             const float* __restrict__ gamma_log) {
    int h = blockIdx.x * blockDim.x + threadIdx.x;
    if (h >= DIM) return;
    float nu = expf(nu_log[h]);
    float th = expf(theta_log[h]);
    float r  = expf(-nu);
    float lr = r * cosf(th);
    float li = r * sinf(th);
    g_lam[h] = make_float2(lr, li);
    float ar = lr, ai = li;
#pragma unroll
    for (int s = 0; s < 6; s++) {
        float nr = ar * ar - ai * ai;
        float ni = 2.0f * ar * ai;
        ar = nr; ai = ni;
    }
    g_lamL[h] = make_float2(ar, ai);
    g_gain[h] = expf(gamma_log[h]);
}

// ---------------- prep: X -> fp16 ----------------
__global__ __launch_bounds__(256) void conv_x(const float* __restrict__ src, int n) {
    int i = (blockIdx.x * blockDim.x + threadIdx.x) * 4;
    if (i >= n) return;
    float4 v = *(const float4*)(src + i);
    __half h4[4];
    h4[0] = __float2half_rn(v.x);
    h4[1] = __float2half_rn(v.y);
    h4[2] = __float2half_rn(v.z);
    h4[3] = __float2half_rn(v.w);
    *(uint2*)(g_x16 + i) = *(uint2*)h4;
}

// ---------------- prep: Cre -> g_cre16, -Cim -> g_cin16 (fused, grid.y=2) ----------------
__global__ __launch_bounds__(256) void conv_c(const float* __restrict__ Cre,
                                              const float* __restrict__ Cim) {
    int z = blockIdx.y;
    const float* src = z ? Cim : Cre;
    __half* dst = z ? g_cin16 : g_cre16;
    float sign = z ? -1.0f : 1.0f;
    int i = (blockIdx.x * blockDim.x + threadIdx.x) * 4;
    float4 v = *(const float4*)(src + i);
    __half h4[4];
    h4[0] = __float2half_rn(v.x * sign);
    h4[1] = __float2half_rn(v.y * sign);
    h4[2] = __float2half_rn(v.z * sign);
    h4[3] = __float2half_rn(v.w * sign);
    *(uint2*)(dst + i) = *(uint2*)h4;
}

// ---------------- prep: transpose + fp16 for Bre/Bim (gain-scaled) and D (fused, grid.z=3) ----------------
__global__ void transpose_conv(const float* __restrict__ Bre,
                               const float* __restrict__ Bim,
                               const float* __restrict__ Dm) {
    __shared__ float tl[32][33];
    int mode = blockIdx.z;
    const float* src = (mode == 0) ? Bre : (mode == 1 ? Bim : Dm);
    __half* dst = (mode == 0) ? g_brt16 : (mode == 1 ? g_bit16 : g_dt16);
    bool use_gain = (mode != 2);
    int bx = blockIdx.x * 32, by = blockIdx.y * 32;
    int tx = threadIdx.x, ty = threadIdx.y;
#pragma unroll
    for (int r = 0; r < 4; r++) {
        int row = by + ty + r * 8;
        float v = src[(size_t)row * DIM + bx + tx];
        if (use_gain) v *= g_gain[row];
        tl[ty + r * 8][tx] = v;
    }
    __syncthreads();
#pragma unroll
    for (int r = 0; r < 4; r++) {
        float v = tl[tx][ty + r * 8];
        size_t o = (size_t)(bx + ty + r * 8) * DIM + by + tx;
        dst[o] = __float2half_rn(v);
    }
}

// ================= generic TN fp16 GEMM, BM=BN=128, BK=64, 3-stage ring =================
// smem: 3 x (A 16KB + B 16KB) = 96KB; regs capped for 2 CTAs/SM.
// Inner loop register-pipelined: next A/B fragments prefetched during MMAs.
// mode 0: Bu (z = re/im, fp16 store). mode 1: out = C-term + D-term (3 fused passes).

__device__ __forceinline__ void pass_ptrs(int mode, int z, int kt,
        const __half*& A, const __half*& B, int& k0) {
    if (mode == 0) {
        A = g_x16; B = z ? g_bit16 : g_brt16; k0 = kt * 64;
    } else {
        int p = kt >> 4; k0 = (kt & 15) * 64;
        switch (p) {
            case 0:  A = g_hre16; B = g_cre16; break;
            case 1:  A = g_him16; B = g_cin16; break;
            default: A = g_x16;   B = g_dt16;  break;
        }
    }
}

__global__ __launch_bounds__(256, 2) void gemm_mma(int mode, float* __restrict__ outp) {
    extern __shared__ __align__(128) char sm[];
    unsigned sbase = smem_u32(sm);
    const int tid = threadIdx.x, lane = tid & 31, w = tid >> 5;
    const int wm = w & 1, wn = w >> 1;
    const int n0 = blockIdx.x * 128, m0 = blockIdx.y * 128;
    const int z  = blockIdx.z;
    const int NK = (mode == 0) ? 16 : 48;

    float c[4][4][4];
#pragma unroll
    for (int a = 0; a < 4; a++)
#pragma unroll
        for (int b = 0; b < 4; b++)
#pragma unroll
            for (int d = 0; d < 4; d++) c[a][b][d] = 0.f;

    auto load_stage = [&](int stage, int kt) {
        const __half *A, *B; int k0;
        pass_ptrs(mode, z, kt, A, B, k0);
        unsigned sb = sbase + stage * 32768;
#pragma unroll
        for (int i = 0; i < 4; i++) {
            int idx = tid + i * 256; int row = idx >> 3, g = idx & 7;
            unsigned sw = (unsigned)(row * 128 + ((g ^ (row & 7)) << 4));
            cp16(sb + sw, A + (size_t)(m0 + row) * DIM + k0 + g * 8);
            cp16(sb + 16384 + sw, B + (size_t)(n0 + row) * DIM + k0 + g * 8);
        }
    };

    load_stage(0, 0); CP_COMMIT();
    load_stage(1, 1); CP_COMMIT();

    const int lr = lane & 15, lh = lane >> 4;
    int st = 0;                         // stage holding tile kt
    for (int kt = 0; kt < NK; kt++) {
        CP_WAIT1();
        __syncthreads();
        // issue next global->smem load into the free stage BEFORE compute
        if (kt + 2 < NK) {
            int free_st = st + 2; if (free_st >= 3) free_st -= 3;
            load_stage(free_st, kt + 2);
        }
        CP_COMMIT();
        unsigned sA = sbase + st * 32768;
        unsigned sB = sA + 16384;

        // fragment addresses
        auto a_addr = [&](int ks, int mf) {
            int row = wm * 64 + mf * 16 + lr; int kg = ks * 2 + lh;
            return sA + row * 128 + ((kg ^ (row & 7)) << 4);
        };
        auto b_addr = [&](int ks, int nh) {
            int row = wn * 32 + nh * 16 + lr; int kg = ks * 2 + lh;
            return sB + row * 128 + ((kg ^ (row & 7)) << 4);
        };

        // register-pipelined: prefetch next fragments during MMAs
        uint32_t bb_c[2][4], bb_n[2][4], a_c[4], a_n[4];
        ldsm4(bb_c[0], b_addr(0, 0));
        ldsm4(bb_c[1], b_addr(0, 1));
        ldsm4(a_c, a_addr(0, 0));
#pragma unroll
        for (int ks = 0; ks < 4; ks++) {
#pragma unroll
            for (int mf = 0; mf < 4; mf++) {
                if (mf == 0 && ks < 3) {
                    ldsm4(bb_n[0], b_addr(ks + 1, 0));
                    ldsm4(bb_n[1], b_addr(ks + 1, 1));
                }
                if (mf < 3)      ldsm4(a_n, a_addr(ks, mf + 1));
                else if (ks < 3) ldsm4(a_n, a_addr(ks + 1, 0));
                mma16816(c[mf][0], a_c, bb_c[0][0], bb_c[0][2]);
                mma16816(c[mf][1], a_c, bb_c[0][1], bb_c[0][3]);
                mma16816(c[mf][2], a_c, bb_c[1][0], bb_c[1][2]);
                mma16816(c[mf][3], a_c, bb_c[1][1], bb_c[1][3]);
#pragma unroll
                for (int q = 0; q < 4; q++) a_c[q] = a_n[q];
            }
#pragma unroll
            for (int q = 0; q < 4; q++) { bb_c[0][q] = bb_n[0][q]; bb_c[1][q] = bb_n[1][q]; }
        }
        st++; if (st >= 3) st = 0;
    }

    if (mode == 0) {
        __half* dst = z ? g_buim16 : g_bure16;
#pragma unroll
        for (int mf = 0; mf < 4; mf++) {
#pragma unroll
            for (int nf = 0; nf < 4; nf++) {
                int r   = wm * 64 + mf * 16 + (lane >> 2);
                int col = wn * 32 + nf * 8  + (lane & 3) * 2;
                size_t o = (size_t)(m0 + r) * DIM + n0 + col;
                *(__half2*)(dst + o) = __floats2half2_rn(c[mf][nf][0], c[mf][nf][1]);
                *(__half2*)(dst + o + 8 * DIM) = __floats2half2_rn(c[mf][nf][2], c[mf][nf][3]);
            }
        }
    } else {
#pragma unroll
        for (int mf = 0; mf < 4; mf++) {
#pragma unroll
            for (int nf = 0; nf < 4; nf++) {
                int r   = wm * 64 + mf * 16 + (lane >> 2);
                int col = wn * 32 + nf * 8  + (lane & 3) * 2;
                size_t o = (size_t)(m0 + r) * DIM + n0 + col;
                *(float2*)(outp + o) = make_float2(c[mf][nf][0], c[mf][nf][1]);
                *(float2*)(outp + o + 8 * DIM) = make_float2(c[mf][nf][2], c[mf][nf][3]);
            }
        }
    }
}

// ---------------- scan pass 1: chunk carries (2 channels/thread via __half2, MLP 8) ----------------
__global__ __launch_bounds__(256) void scan_carry() {
    int hp = blockIdx.y * blockDim.x + threadIdx.x;   // channel-pair index
    int h  = hp * 2;
    int c  = blockIdx.x;
    float2 lam0 = g_lam[h], lam1 = g_lam[h + 1];
    float ar0 = 0.f, ai0 = 0.f, ar1 = 0.f, ai1 = 0.f;
    size_t idx = (size_t)c * CLEN * DIM + h;
#pragma unroll 8
    for (int t = 0; t < CLEN; t++, idx += DIM) {
        __half2 br2 = *(const __half2*)(g_bure16 + idx);
        __half2 bi2 = *(const __half2*)(g_buim16 + idx);
        float2 br = __half22float2(br2);
        float2 bi = __half22float2(bi2);
        float nr0 = fmaf(lam0.x, ar0, fmaf(-lam0.y, ai0, br.x));
        float ni0 = fmaf(lam0.x, ai0, fmaf( lam0.y, ar0, bi.x));
        ar0 = nr0; ai0 = ni0;
        float nr1 = fmaf(lam1.x, ar1, fmaf(-lam1.y, ai1, br.y));
        float ni1 = fmaf(lam1.x, ai1, fmaf( lam1.y, ar1, bi.y));
        ar1 = nr1; ai1 = ni1;
    }
    *(float4*)(&g_carry[c * DIM + h]) = make_float4(ar0, ai0, ar1, ai1);
}

// ---------------- scan pass 2: prefix over chunk carries (batched loads for MLP) ----------------
__global__ __launch_bounds__(256) void scan_chunks() {
    int h = blockIdx.x * blockDim.x + threadIdx.x;
    float2 lamL = g_lamL[h];
    float pr = 0.f, pi = 0.f;
    for (int cb = 0; cb < NCHUNK; cb += 32) {
        float2 e[32];
#pragma unroll
        for (int j = 0; j < 32; j++) e[j] = g_carry[(cb + j) * DIM + h];
#pragma unroll
        for (int j = 0; j < 32; j++) {
            float nr = fmaf(lamL.x, pr, fmaf(-lamL.y, pi, e[j].x));
            float ni = fmaf(lamL.x, pi, fmaf( lamL.y, pr, e[j].y));
            pr = nr; pi = ni;
            e[j] = make_float2(pr, pi);
        }
#pragma unroll
        for (int j = 0; j < 32; j++) g_carry2[(cb + j) * DIM + h] = e[j];
    }
}

// ---------------- scan pass 3: apply carry, write fp16 H (2 channels/thread) ----------------
__global__ __launch_bounds__(256) void scan_apply_all() {
    int hp = blockIdx.y * blockDim.x + threadIdx.x;
    int h  = hp * 2;
    int c  = blockIdx.x;
    float4 Pv = (c == 0) ? make_float4(0.f, 0.f, 0.f, 0.f)
                         : *(const float4*)(&g_carry2[(c - 1) * DIM + h]);
    float2 lam0 = g_lam[h], lam1 = g_lam[h + 1];
    float ar0 = Pv.x, ai0 = Pv.y, ar1 = Pv.z, ai1 = Pv.w;
    size_t idx = (size_t)c * CLEN * DIM + h;
#pragma unroll 8
    for (int t = 0; t < CLEN; t++, idx += DIM) {
        __half2 br2 = *(const __half2*)(g_bure16 + idx);
        __half2 bi2 = *(const __half2*)(g_buim16 + idx);
        float2 br = __half22float2(br2);
        float2 bi = __half22float2(bi2);
        float nr0 = fmaf(lam0.x, ar0, fmaf(-lam0.y, ai0, br.x));
        float ni0 = fmaf(lam0.x, ai0, fmaf( lam0.y, ar0, bi.x));
        ar0 = nr0; ai0 = ni0;
        float nr1 = fmaf(lam1.x, ar1, fmaf(-lam1.y, ai1, br.y));
        float ni1 = fmaf(lam1.x, ai1, fmaf( lam1.y, ar1, bi.y));
        ar1 = nr1; ai1 = ni1;
        *(__half2*)(g_hre16 + idx) = __floats2half2_rn(ar0, ar1);
        *(__half2*)(g_him16 + idx) = __floats2half2_rn(ai0, ai1);
    }
}

// ---------------- launch (serial chain) ----------------
extern "C" void kernel_launch(void* const* d_in, const int* in_sizes, int n_in,
                              void* d_out, int out_size) {
    const float* X         = (const float*)d_in[0];
    const float* nu_log    = (const float*)d_in[1];
    const float* theta_log = (const float*)d_in[2];
    const float* gamma_log = (const float*)d_in[3];
    const float* Bre       = (const float*)d_in[4];
    const float* Bim       = (const float*)d_in[5];
    const float* Cre       = (const float*)d_in[6];
    const float* Cim       = (const float*)d_in[7];
    const float* Dm        = (const float*)d_in[8];
    float* out             = (float*)d_out;

    cudaFuncSetAttribute(gemm_mma, cudaFuncAttributeMaxDynamicSharedMemorySize, 98304);

    setup_kernel<<<4, 256>>>(nu_log, theta_log, gamma_log);
    conv_x<<<T_LEN * DIM / 4 / 256, 256>>>(X, T_LEN * DIM);
    conv_c<<<dim3(DIM * DIM / 4 / 256, 2), 256>>>(Cre, Cim);
    transpose_conv<<<dim3(32, 32, 3), dim3(32, 8)>>>(Bre, Bim, Dm);

    // GEMM1: Bu_re / Bu_im via blockIdx.z, fp16 output
    gemm_mma<<<dim3(DIM / 128, T_LEN / 128, 2), 256, 98304>>>(0, nullptr);

    scan_carry<<<dim3(NCHUNK, DIM / 512), 256>>>();
    scan_chunks<<<DIM / 256, 256>>>();
    scan_apply_all<<<dim3(NCHUNK, DIM / 512), 256>>>();

    // GEMM2: out = Hr@Cre^T + Hi@(-Cim)^T + X@D  (3 fused passes, 48 k-tiles)
    gemm_mma<<<dim3(DIM / 128, T_LEN / 128, 1), 256, 98304>>>(1, out);
}